// round 14
// baseline (speedup 1.0000x reference)
#include <cuda_runtime.h>
#include <cuda_fp16.h>
#include <cstdint>

// out[M,N] = x[M,K] @ W[N,K]^T + bias ; M=8192, N=4096, K=1024 (fp32)
// Round 14: R11 core restored (it sits at 96% of the mma.sync issue floor,
// 3 cyc/MMA/SM). Only provably-safe trims: hoist cp.async issues ahead of
// compute in each window, hoisted-bias epilogue, MLP-2 prep.

#define MDIM 8192
#define NDIM 4096
#define KDIM 1024

#define BM 256
#define BN 128
#define BK 32                 // fp16: 64 B per row per plane
#define STAGES 6
#define NCHUNK (KDIM / BK)    // 32
#define NPAIR (NCHUNK / 2)    // 16

#define APLANEB (BM * 64)     // 16384 B
#define BPLANEB (BN * 64)     // 8192 B
#define OFF_A 0
#define OFF_B (APLANEB)
#define STAGEB (APLANEB + BPLANEB)    // 24576
#define SMEM_TOTAL (STAGES * STAGEB)  // 147456

// XOR swizzle on 16B chunks within 64B rows (conflict-free ldmatrix + cp.async)
#define SWZ(a) ((a) ^ (((a) >> 3) & 0x30))

// ---- static scratch for fp16 operands ----
__device__ __align__(256) __half g_A[MDIM * KDIM];
__device__ __align__(256) __half g_B[NDIM * KDIM];

// ================= PTX helpers (base PTX only) =================
__device__ __forceinline__ uint32_t smem_u32(const void* p) {
    uint32_t a;
    asm("{ .reg .u64 t; cvta.to.shared.u64 t, %1; cvt.u32.u64 %0, t; }" : "=r"(a) : "l"(p));
    return a;
}
__device__ __forceinline__ void cp16(uint32_t dst, const void* src) {
    asm volatile("cp.async.cg.shared.global [%0], [%1], 16;" :: "r"(dst), "l"(src));
}
#define CP_COMMIT() asm volatile("cp.async.commit_group;" ::: "memory")
#define CP_WAIT2()  asm volatile("cp.async.wait_group 2;"  ::: "memory")
#define CP_WAIT0()  asm volatile("cp.async.wait_group 0;"  ::: "memory")

__device__ __forceinline__ void ldm_x4(uint32_t* r, uint32_t addr) {
    asm volatile("ldmatrix.sync.aligned.m8n8.x4.shared.b16 {%0,%1,%2,%3}, [%4];"
        : "=r"(r[0]), "=r"(r[1]), "=r"(r[2]), "=r"(r[3]) : "r"(addr));
}
__device__ __forceinline__ void mma16816(float* d, const uint32_t* a, const uint32_t* b) {
    asm volatile("mma.sync.aligned.m16n8k16.row.col.f32.f16.f16.f32 "
        "{%0,%1,%2,%3}, {%4,%5,%6,%7}, {%8,%9}, {%0,%1,%2,%3};"
        : "+f"(d[0]), "+f"(d[1]), "+f"(d[2]), "+f"(d[3])
        : "r"(a[0]), "r"(a[1]), "r"(a[2]), "r"(a[3]), "r"(b[0]), "r"(b[1]));
}

// ================= prep: fp32 -> fp16, 2 float4s per thread =================
__global__ void prep_kernel(const float* __restrict__ x,
                            const float* __restrict__ w,
                            int n4x, int n4tot)
{
    int i0 = (blockIdx.x * blockDim.x + threadIdx.x) * 2;
    #pragma unroll
    for (int u = 0; u < 2; u++) {
        int i = i0 + u;
        if (i >= n4tot) return;
        const float* src;
        __half* dst;
        int idx;
        if (i < n4x) { src = x; dst = g_A; idx = i; }
        else         { src = w; dst = g_B; idx = i - n4x; }
        float4 v = reinterpret_cast<const float4*>(src)[idx];
        ushort4 o;
        o.x = ((__half_raw)__float2half_rn(v.x)).x;
        o.y = ((__half_raw)__float2half_rn(v.y)).x;
        o.z = ((__half_raw)__float2half_rn(v.z)).x;
        o.w = ((__half_raw)__float2half_rn(v.w)).x;
        reinterpret_cast<ushort4*>(dst)[idx] = o;
    }
}

// ================= main GEMM kernel =================
__global__ void __launch_bounds__(512, 1)
qgemm_fp16(const float* __restrict__ bias, float* __restrict__ C)
{
    extern __shared__ char smem[];
    const uint32_t sbase = smem_u32(smem);
    const int tid  = threadIdx.x;
    const int wid  = tid >> 5;
    const int lane = tid & 31;
    const int bm = blockIdx.y * BM;
    const int bn = blockIdx.x * BN;
    const int wm = (wid >> 2) * 64;   // warp row offset (0,64,128,192)
    const int wn = (wid & 3) * 32;    // warp col offset (0,32,64,96)

    float acc[4][4][4];
    #pragma unroll
    for (int a = 0; a < 4; a++)
        #pragma unroll
        for (int b = 0; b < 4; b++)
            #pragma unroll
            for (int k = 0; k < 4; k++)
                acc[a][b][k] = 0.0f;

    // loader coords (512 threads: A plane 2 chunks/thread, B plane 1)
    const int a0row = tid >> 2,         a0c = tid & 3;
    const int a1row = (tid + 512) >> 2;
    const uint32_t dswA0 = SWZ((uint32_t)(a0row * 64 + a0c * 16));
    const uint32_t dswA1 = SWZ((uint32_t)(a1row * 64 + a0c * 16));
    const char* pA0 = (const char*)g_A + (size_t)(bm + a0row) * (KDIM * 2) + a0c * 16;
    const char* pA1 = (const char*)g_A + (size_t)(bm + a1row) * (KDIM * 2) + a0c * 16;
    const char* pB  = (const char*)g_B + (size_t)(bn + a0row) * (KDIM * 2) + a0c * 16;

    auto issue = [&](int chunk) {
        const uint32_t sst = sbase + (chunk % STAGES) * STAGEB;
        const size_t ko = (size_t)chunk * (BK * 2);
        cp16(sst + OFF_A + dswA0, pA0 + ko);
        cp16(sst + OFF_A + dswA1, pA1 + ko);
        cp16(sst + OFF_B + dswA0, pB + ko);
        CP_COMMIT();
    };
    issue(0); issue(1); issue(2); issue(3);

    // ldmatrix fragment offsets (plane-relative, swizzled), ks = k16 half
    uint32_t aoff[4][2], boff[2][2];
    #pragma unroll
    for (int mb = 0; mb < 4; mb++)
        #pragma unroll
        for (int ks = 0; ks < 2; ks++)
            aoff[mb][ks] = SWZ((uint32_t)((wm + mb * 16 + (lane & 15)) * 64 +
                                          ks * 32 + (lane >> 4) * 16));
    #pragma unroll
    for (int p = 0; p < 2; p++)
        #pragma unroll
        for (int ks = 0; ks < 2; ks++)
            boff[p][ks] = SWZ((uint32_t)((wn + p * 16 + (lane & 7) + ((lane >> 4) << 3)) * 64 +
                                         ks * 32 + ((lane >> 3) & 1) * 16));

    auto do_ks = [&](int chunk, int ks) {
        const uint32_t sst = sbase + (chunk % STAGES) * STAGEB;
        uint32_t bh[4][2];
        #pragma unroll
        for (int p = 0; p < 2; p++) {
            uint32_t r[4];
            ldm_x4(r, sst + OFF_B + boff[p][ks]);
            bh[p*2][0] = r[0]; bh[p*2][1] = r[1];
            bh[p*2+1][0] = r[2]; bh[p*2+1][1] = r[3];
        }
        #pragma unroll
        for (int mb = 0; mb < 4; mb++) {
            uint32_t ah[4];
            ldm_x4(ah, sst + OFF_A + aoff[mb][ks]);
            #pragma unroll
            for (int nb = 0; nb < 4; nb++)
                mma16816(acc[mb][nb], ah, bh[nb]);
        }
    };

    for (int p = 0; p < NPAIR; p++) {
        const int c = 2 * p;
        if (p == NPAIR - 1) { CP_WAIT0(); } else { CP_WAIT2(); }
        __syncthreads();

        // issue next window's loads FIRST so they fly under this window's MMAs
        if (c + 4 < NCHUNK) issue(c + 4);
        if (c + 5 < NCHUNK) issue(c + 5);

        do_ks(c, 0);     do_ks(c, 1);
        do_ks(c + 1, 0); do_ks(c + 1, 1);
    }

    // -------- epilogue: + bias (hoisted), store --------
    const int g  = lane >> 2;
    const int tg = lane & 3;
    float2 bv[4];
    #pragma unroll
    for (int nb = 0; nb < 4; nb++)
        bv[nb] = *reinterpret_cast<const float2*>(bias + bn + wn + nb * 8 + tg * 2);

    #pragma unroll
    for (int mb = 0; mb < 4; mb++) {
        const int r0 = bm + wm + mb * 16 + g;
        #pragma unroll
        for (int nb = 0; nb < 4; nb++) {
            const int col = bn + wn + nb * 8 + tg * 2;
            float2 o0 = {acc[mb][nb][0] + bv[nb].x, acc[mb][nb][1] + bv[nb].y};
            float2 o1 = {acc[mb][nb][2] + bv[nb].x, acc[mb][nb][3] + bv[nb].y};
            *reinterpret_cast<float2*>(C + (size_t)r0 * NDIM + col) = o0;
            *reinterpret_cast<float2*>(C + (size_t)(r0 + 8) * NDIM + col) = o1;
        }
    }
}

// ================= host side =================
extern "C" void kernel_launch(void* const* d_in, const int* in_sizes, int n_in,
                              void* d_out, int out_size)
{
    const float* x    = (const float*)d_in[0];   // [M, K]
    const float* w    = (const float*)d_in[1];   // [N, K]
    const float* bias = (const float*)d_in[2];   // [N]
    float* out        = (float*)d_out;           // [M, N]

    const int n4x = MDIM * KDIM / 4;
    const int n4w = NDIM * KDIM / 4;
    const int n4tot = n4x + n4w;
    prep_kernel<<<(n4tot / 2 + 255) / 256, 256>>>(x, w, n4x, n4tot);

    static bool attr_set = false;
    if (!attr_set) {
        cudaFuncSetAttribute(qgemm_fp16, cudaFuncAttributeMaxDynamicSharedMemorySize, SMEM_TOTAL);
        attr_set = true;
    }
    dim3 grid(NDIM / BN, MDIM / BM);   // (32, 32) = 1024 CTAs
    qgemm_fp16<<<grid, 512, SMEM_TOTAL>>>(bias, out);
}

// round 15
// speedup vs baseline: 1.1061x; 1.1061x over previous
#include <cuda_runtime.h>
#include <cuda_fp16.h>
#include <cstdint>

// out[M,N] = x[M,K] @ W[N,K]^T + bias ; M=8192, N=4096, K=1024 (fp32)
// Round 15: GEMM kernel is R11 BYTE-FOR-BYTE (local optimum: 96% of the
// measured mma.sync floor of 3 cyc/MMA/SM; every scheduling tweak regressed).
// Only the prep kernel changes: MLP-4 loads + f16x2 packed converts.

#define MDIM 8192
#define NDIM 4096
#define KDIM 1024

#define BM 256
#define BN 128
#define BK 32                 // fp16: 64 B per row per plane
#define STAGES 6
#define NCHUNK (KDIM / BK)    // 32
#define NPAIR (NCHUNK / 2)    // 16

#define APLANEB (BM * 64)     // 16384 B
#define BPLANEB (BN * 64)     // 8192 B
#define OFF_A 0
#define OFF_B (APLANEB)
#define STAGEB (APLANEB + BPLANEB)    // 24576
#define SMEM_TOTAL (STAGES * STAGEB)  // 147456

// XOR swizzle on 16B chunks within 64B rows (conflict-free ldmatrix + cp.async)
#define SWZ(a) ((a) ^ (((a) >> 3) & 0x30))

// ---- static scratch for fp16 operands ----
__device__ __align__(256) __half g_A[MDIM * KDIM];
__device__ __align__(256) __half g_B[NDIM * KDIM];

// ================= PTX helpers (base PTX only) =================
__device__ __forceinline__ uint32_t smem_u32(const void* p) {
    uint32_t a;
    asm("{ .reg .u64 t; cvta.to.shared.u64 t, %1; cvt.u32.u64 %0, t; }" : "=r"(a) : "l"(p));
    return a;
}
__device__ __forceinline__ void cp16(uint32_t dst, const void* src) {
    asm volatile("cp.async.cg.shared.global [%0], [%1], 16;" :: "r"(dst), "l"(src));
}
#define CP_COMMIT() asm volatile("cp.async.commit_group;" ::: "memory")
#define CP_WAIT2()  asm volatile("cp.async.wait_group 2;"  ::: "memory")
#define CP_WAIT0()  asm volatile("cp.async.wait_group 0;"  ::: "memory")

__device__ __forceinline__ void ldm_x4(uint32_t* r, uint32_t addr) {
    asm volatile("ldmatrix.sync.aligned.m8n8.x4.shared.b16 {%0,%1,%2,%3}, [%4];"
        : "=r"(r[0]), "=r"(r[1]), "=r"(r[2]), "=r"(r[3]) : "r"(addr));
}
__device__ __forceinline__ void mma16816(float* d, const uint32_t* a, const uint32_t* b) {
    asm volatile("mma.sync.aligned.m16n8k16.row.col.f32.f16.f16.f32 "
        "{%0,%1,%2,%3}, {%4,%5,%6,%7}, {%8,%9}, {%0,%1,%2,%3};"
        : "+f"(d[0]), "+f"(d[1]), "+f"(d[2]), "+f"(d[3])
        : "r"(a[0]), "r"(a[1]), "r"(a[2]), "r"(a[3]), "r"(b[0]), "r"(b[1]));
}

// ============ prep: fp32 -> fp16, 4 independent float4 per thread ==========
__device__ __forceinline__ uint32_t pack_h2(float lo, float hi) {
    uint32_t r;
    asm("cvt.rn.f16x2.f32 %0, %1, %2;" : "=r"(r) : "f"(hi), "f"(lo));
    return r;
}
__global__ void prep_kernel(const float* __restrict__ x,
                            const float* __restrict__ w,
                            int n4x, int n4tot)
{
    const int base = (blockIdx.x * blockDim.x + threadIdx.x) * 4;
    if (base >= n4tot) return;
    const float* src;
    __half* dst;
    int idx;
    if (base < n4x) { src = x; dst = g_A; idx = base; }       // n4x % 4 == 0
    else            { src = w; dst = g_B; idx = base - n4x; }

    // 4 independent loads in flight (MLP=4 overlaps DRAM + PTW latency)
    float4 v0 = reinterpret_cast<const float4*>(src)[idx + 0];
    float4 v1 = reinterpret_cast<const float4*>(src)[idx + 1];
    float4 v2 = reinterpret_cast<const float4*>(src)[idx + 2];
    float4 v3 = reinterpret_cast<const float4*>(src)[idx + 3];

    uint2 o0 = {pack_h2(v0.x, v0.y), pack_h2(v0.z, v0.w)};
    uint2 o1 = {pack_h2(v1.x, v1.y), pack_h2(v1.z, v1.w)};
    uint2 o2 = {pack_h2(v2.x, v2.y), pack_h2(v2.z, v2.w)};
    uint2 o3 = {pack_h2(v3.x, v3.y), pack_h2(v3.z, v3.w)};

    reinterpret_cast<uint2*>(dst)[idx + 0] = o0;
    reinterpret_cast<uint2*>(dst)[idx + 1] = o1;
    reinterpret_cast<uint2*>(dst)[idx + 2] = o2;
    reinterpret_cast<uint2*>(dst)[idx + 3] = o3;
}

// ================= main GEMM kernel (R11, unmodified) =================
__global__ void __launch_bounds__(512, 1)
qgemm_fp16(const float* __restrict__ bias, float* __restrict__ C)
{
    extern __shared__ char smem[];
    const uint32_t sbase = smem_u32(smem);
    const int tid  = threadIdx.x;
    const int wid  = tid >> 5;
    const int lane = tid & 31;
    const int bm = blockIdx.y * BM;
    const int bn = blockIdx.x * BN;
    const int wm = (wid >> 2) * 64;   // warp row offset (0,64,128,192)
    const int wn = (wid & 3) * 32;    // warp col offset (0,32,64,96)

    float acc[4][4][4];
    #pragma unroll
    for (int a = 0; a < 4; a++)
        #pragma unroll
        for (int b = 0; b < 4; b++)
            #pragma unroll
            for (int k = 0; k < 4; k++)
                acc[a][b][k] = 0.0f;

    // loader coords (512 threads: A plane 2 chunks/thread, B plane 1)
    const int a0row = tid >> 2,         a0c = tid & 3;
    const int a1row = (tid + 512) >> 2;
    const uint32_t dswA0 = SWZ((uint32_t)(a0row * 64 + a0c * 16));
    const uint32_t dswA1 = SWZ((uint32_t)(a1row * 64 + a0c * 16));
    const char* pA0 = (const char*)g_A + (size_t)(bm + a0row) * (KDIM * 2) + a0c * 16;
    const char* pA1 = (const char*)g_A + (size_t)(bm + a1row) * (KDIM * 2) + a0c * 16;
    const char* pB  = (const char*)g_B + (size_t)(bn + a0row) * (KDIM * 2) + a0c * 16;

    auto issue = [&](int chunk) {
        const uint32_t sst = sbase + (chunk % STAGES) * STAGEB;
        const size_t ko = (size_t)chunk * (BK * 2);
        cp16(sst + OFF_A + dswA0, pA0 + ko);
        cp16(sst + OFF_A + dswA1, pA1 + ko);
        cp16(sst + OFF_B + dswA0, pB + ko);
        CP_COMMIT();
    };
    issue(0); issue(1); issue(2); issue(3);

    // ldmatrix fragment offsets (plane-relative, swizzled), ks = k16 half
    uint32_t aoff[4][2], boff[2][2];
    #pragma unroll
    for (int mb = 0; mb < 4; mb++)
        #pragma unroll
        for (int ks = 0; ks < 2; ks++)
            aoff[mb][ks] = SWZ((uint32_t)((wm + mb * 16 + (lane & 15)) * 64 +
                                          ks * 32 + (lane >> 4) * 16));
    #pragma unroll
    for (int p = 0; p < 2; p++)
        #pragma unroll
        for (int ks = 0; ks < 2; ks++)
            boff[p][ks] = SWZ((uint32_t)((wn + p * 16 + (lane & 7) + ((lane >> 4) << 3)) * 64 +
                                         ks * 32 + ((lane >> 3) & 1) * 16));

    auto do_ks = [&](int chunk, int ks) {
        const uint32_t sst = sbase + (chunk % STAGES) * STAGEB;
        uint32_t bh[4][2];
        #pragma unroll
        for (int p = 0; p < 2; p++) {
            uint32_t r[4];
            ldm_x4(r, sst + OFF_B + boff[p][ks]);
            bh[p*2][0] = r[0]; bh[p*2][1] = r[1];
            bh[p*2+1][0] = r[2]; bh[p*2+1][1] = r[3];
        }
        #pragma unroll
        for (int mb = 0; mb < 4; mb++) {
            uint32_t ah[4];
            ldm_x4(ah, sst + OFF_A + aoff[mb][ks]);
            #pragma unroll
            for (int nb = 0; nb < 4; nb++)
                mma16816(acc[mb][nb], ah, bh[nb]);
        }
    };

    for (int p = 0; p < NPAIR; p++) {
        const int c = 2 * p;
        if (p == NPAIR - 1) { CP_WAIT0(); } else { CP_WAIT2(); }
        __syncthreads();

        do_ks(c, 0);     do_ks(c, 1);
        do_ks(c + 1, 0); do_ks(c + 1, 1);

        if (c + 4 < NCHUNK) issue(c + 4);
        if (c + 5 < NCHUNK) issue(c + 5);
    }

    // -------- epilogue: + bias, store --------
    const int g  = lane >> 2;
    const int tg = lane & 3;
    #pragma unroll
    for (int mb = 0; mb < 4; mb++) {
        #pragma unroll
        for (int nb = 0; nb < 4; nb++) {
            const int col = bn + wn + nb * 8 + tg * 2;
            const float2 bv = *reinterpret_cast<const float2*>(bias + col);
            const int r0 = bm + wm + mb * 16 + g;
            float2 o0 = {acc[mb][nb][0] + bv.x, acc[mb][nb][1] + bv.y};
            float2 o1 = {acc[mb][nb][2] + bv.x, acc[mb][nb][3] + bv.y};
            *reinterpret_cast<float2*>(C + (size_t)r0 * NDIM + col) = o0;
            *reinterpret_cast<float2*>(C + (size_t)(r0 + 8) * NDIM + col) = o1;
        }
    }
}

// ================= host side =================
extern "C" void kernel_launch(void* const* d_in, const int* in_sizes, int n_in,
                              void* d_out, int out_size)
{
    const float* x    = (const float*)d_in[0];   // [M, K]
    const float* w    = (const float*)d_in[1];   // [N, K]
    const float* bias = (const float*)d_in[2];   // [N]
    float* out        = (float*)d_out;           // [M, N]

    const int n4x = MDIM * KDIM / 4;             // 2097152 (div by 4)
    const int n4w = NDIM * KDIM / 4;             // 1048576 (div by 4)
    const int n4tot = n4x + n4w;
    prep_kernel<<<(n4tot / 4 + 255) / 256, 256>>>(x, w, n4x, n4tot);

    static bool attr_set = false;
    if (!attr_set) {
        cudaFuncSetAttribute(qgemm_fp16, cudaFuncAttributeMaxDynamicSharedMemorySize, SMEM_TOTAL);
        attr_set = true;
    }
    dim3 grid(NDIM / BN, MDIM / BM);   // (32, 32) = 1024 CTAs
    qgemm_fp16<<<grid, 512, SMEM_TOTAL>>>(bias, out);
}

// round 16
// speedup vs baseline: 1.1299x; 1.0215x over previous
#include <cuda_runtime.h>
#include <cuda_fp16.h>
#include <cstdint>

// out[M,N] = x[M,K] @ W[N,K]^T + bias ; M=8192, N=4096, K=1024 (fp32)
// Round 16: composition of best-measured parts.
//   GEMM: R11 byte-for-byte (96% of the mma.sync issue floor, 3 cyc/MMA/SM;
//         every scheduling perturbation across R12-R14 regressed).
//   Prep: MLP-2 variant (fastest measured: 13.3us overhead in R14) with
//         __ldcs streaming loads (fp32 inputs are never re-read; keep L2
//         for the fp16 outputs that GEMM chunk-0 re-reads) and packed
//         cvt.rn.f16x2 converts.

#define MDIM 8192
#define NDIM 4096
#define KDIM 1024

#define BM 256
#define BN 128
#define BK 32                 // fp16: 64 B per row per plane
#define STAGES 6
#define NCHUNK (KDIM / BK)    // 32
#define NPAIR (NCHUNK / 2)    // 16

#define APLANEB (BM * 64)     // 16384 B
#define BPLANEB (BN * 64)     // 8192 B
#define OFF_A 0
#define OFF_B (APLANEB)
#define STAGEB (APLANEB + BPLANEB)    // 24576
#define SMEM_TOTAL (STAGES * STAGEB)  // 147456

// XOR swizzle on 16B chunks within 64B rows (conflict-free ldmatrix + cp.async)
#define SWZ(a) ((a) ^ (((a) >> 3) & 0x30))

// ---- static scratch for fp16 operands ----
__device__ __align__(256) __half g_A[MDIM * KDIM];
__device__ __align__(256) __half g_B[NDIM * KDIM];

// ================= PTX helpers (base PTX only) =================
__device__ __forceinline__ uint32_t smem_u32(const void* p) {
    uint32_t a;
    asm("{ .reg .u64 t; cvta.to.shared.u64 t, %1; cvt.u32.u64 %0, t; }" : "=r"(a) : "l"(p));
    return a;
}
__device__ __forceinline__ void cp16(uint32_t dst, const void* src) {
    asm volatile("cp.async.cg.shared.global [%0], [%1], 16;" :: "r"(dst), "l"(src));
}
#define CP_COMMIT() asm volatile("cp.async.commit_group;" ::: "memory")
#define CP_WAIT2()  asm volatile("cp.async.wait_group 2;"  ::: "memory")
#define CP_WAIT0()  asm volatile("cp.async.wait_group 0;"  ::: "memory")

__device__ __forceinline__ void ldm_x4(uint32_t* r, uint32_t addr) {
    asm volatile("ldmatrix.sync.aligned.m8n8.x4.shared.b16 {%0,%1,%2,%3}, [%4];"
        : "=r"(r[0]), "=r"(r[1]), "=r"(r[2]), "=r"(r[3]) : "r"(addr));
}
__device__ __forceinline__ void mma16816(float* d, const uint32_t* a, const uint32_t* b) {
    asm volatile("mma.sync.aligned.m16n8k16.row.col.f32.f16.f16.f32 "
        "{%0,%1,%2,%3}, {%4,%5,%6,%7}, {%8,%9}, {%0,%1,%2,%3};"
        : "+f"(d[0]), "+f"(d[1]), "+f"(d[2]), "+f"(d[3])
        : "r"(a[0]), "r"(a[1]), "r"(a[2]), "r"(a[3]), "r"(b[0]), "r"(b[1]));
}

// ======== prep: fp32 -> fp16, 2 float4s per thread, streaming loads ========
__device__ __forceinline__ uint32_t pack_h2(float lo, float hi) {
    uint32_t r;
    asm("cvt.rn.f16x2.f32 %0, %1, %2;" : "=r"(r) : "f"(hi), "f"(lo));
    return r;
}
__global__ void prep_kernel(const float* __restrict__ x,
                            const float* __restrict__ w,
                            int n4x, int n4tot)
{
    int i0 = (blockIdx.x * blockDim.x + threadIdx.x) * 2;
    #pragma unroll
    for (int u = 0; u < 2; u++) {
        int i = i0 + u;
        if (i >= n4tot) return;
        const float* src;
        __half* dst;
        int idx;
        if (i < n4x) { src = x; dst = g_A; idx = i; }
        else         { src = w; dst = g_B; idx = i - n4x; }
        float4 v = __ldcs(reinterpret_cast<const float4*>(src) + idx);  // evict-first
        uint2 o = {pack_h2(v.x, v.y), pack_h2(v.z, v.w)};
        reinterpret_cast<uint2*>(dst)[idx] = o;
    }
}

// ================= main GEMM kernel (R11, unmodified) =================
__global__ void __launch_bounds__(512, 1)
qgemm_fp16(const float* __restrict__ bias, float* __restrict__ C)
{
    extern __shared__ char smem[];
    const uint32_t sbase = smem_u32(smem);
    const int tid  = threadIdx.x;
    const int wid  = tid >> 5;
    const int lane = tid & 31;
    const int bm = blockIdx.y * BM;
    const int bn = blockIdx.x * BN;
    const int wm = (wid >> 2) * 64;   // warp row offset (0,64,128,192)
    const int wn = (wid & 3) * 32;    // warp col offset (0,32,64,96)

    float acc[4][4][4];
    #pragma unroll
    for (int a = 0; a < 4; a++)
        #pragma unroll
        for (int b = 0; b < 4; b++)
            #pragma unroll
            for (int k = 0; k < 4; k++)
                acc[a][b][k] = 0.0f;

    // loader coords (512 threads: A plane 2 chunks/thread, B plane 1)
    const int a0row = tid >> 2,         a0c = tid & 3;
    const int a1row = (tid + 512) >> 2;
    const uint32_t dswA0 = SWZ((uint32_t)(a0row * 64 + a0c * 16));
    const uint32_t dswA1 = SWZ((uint32_t)(a1row * 64 + a0c * 16));
    const char* pA0 = (const char*)g_A + (size_t)(bm + a0row) * (KDIM * 2) + a0c * 16;
    const char* pA1 = (const char*)g_A + (size_t)(bm + a1row) * (KDIM * 2) + a0c * 16;
    const char* pB  = (const char*)g_B + (size_t)(bn + a0row) * (KDIM * 2) + a0c * 16;

    auto issue = [&](int chunk) {
        const uint32_t sst = sbase + (chunk % STAGES) * STAGEB;
        const size_t ko = (size_t)chunk * (BK * 2);
        cp16(sst + OFF_A + dswA0, pA0 + ko);
        cp16(sst + OFF_A + dswA1, pA1 + ko);
        cp16(sst + OFF_B + dswA0, pB + ko);
        CP_COMMIT();
    };
    issue(0); issue(1); issue(2); issue(3);

    // ldmatrix fragment offsets (plane-relative, swizzled), ks = k16 half
    uint32_t aoff[4][2], boff[2][2];
    #pragma unroll
    for (int mb = 0; mb < 4; mb++)
        #pragma unroll
        for (int ks = 0; ks < 2; ks++)
            aoff[mb][ks] = SWZ((uint32_t)((wm + mb * 16 + (lane & 15)) * 64 +
                                          ks * 32 + (lane >> 4) * 16));
    #pragma unroll
    for (int p = 0; p < 2; p++)
        #pragma unroll
        for (int ks = 0; ks < 2; ks++)
            boff[p][ks] = SWZ((uint32_t)((wn + p * 16 + (lane & 7) + ((lane >> 4) << 3)) * 64 +
                                         ks * 32 + ((lane >> 3) & 1) * 16));

    auto do_ks = [&](int chunk, int ks) {
        const uint32_t sst = sbase + (chunk % STAGES) * STAGEB;
        uint32_t bh[4][2];
        #pragma unroll
        for (int p = 0; p < 2; p++) {
            uint32_t r[4];
            ldm_x4(r, sst + OFF_B + boff[p][ks]);
            bh[p*2][0] = r[0]; bh[p*2][1] = r[1];
            bh[p*2+1][0] = r[2]; bh[p*2+1][1] = r[3];
        }
        #pragma unroll
        for (int mb = 0; mb < 4; mb++) {
            uint32_t ah[4];
            ldm_x4(ah, sst + OFF_A + aoff[mb][ks]);
            #pragma unroll
            for (int nb = 0; nb < 4; nb++)
                mma16816(acc[mb][nb], ah, bh[nb]);
        }
    };

    for (int p = 0; p < NPAIR; p++) {
        const int c = 2 * p;
        if (p == NPAIR - 1) { CP_WAIT0(); } else { CP_WAIT2(); }
        __syncthreads();

        do_ks(c, 0);     do_ks(c, 1);
        do_ks(c + 1, 0); do_ks(c + 1, 1);

        if (c + 4 < NCHUNK) issue(c + 4);
        if (c + 5 < NCHUNK) issue(c + 5);
    }

    // -------- epilogue: + bias, store --------
    const int g  = lane >> 2;
    const int tg = lane & 3;
    #pragma unroll
    for (int mb = 0; mb < 4; mb++) {
        #pragma unroll
        for (int nb = 0; nb < 4; nb++) {
            const int col = bn + wn + nb * 8 + tg * 2;
            const float2 bv = *reinterpret_cast<const float2*>(bias + col);
            const int r0 = bm + wm + mb * 16 + g;
            float2 o0 = {acc[mb][nb][0] + bv.x, acc[mb][nb][1] + bv.y};
            float2 o1 = {acc[mb][nb][2] + bv.x, acc[mb][nb][3] + bv.y};
            *reinterpret_cast<float2*>(C + (size_t)r0 * NDIM + col) = o0;
            *reinterpret_cast<float2*>(C + (size_t)(r0 + 8) * NDIM + col) = o1;
        }
    }
}

// ================= host side =================
extern "C" void kernel_launch(void* const* d_in, const int* in_sizes, int n_in,
                              void* d_out, int out_size)
{
    const float* x    = (const float*)d_in[0];   // [M, K]
    const float* w    = (const float*)d_in[1];   // [N, K]
    const float* bias = (const float*)d_in[2];   // [N]
    float* out        = (float*)d_out;           // [M, N]

    const int n4x = MDIM * KDIM / 4;
    const int n4w = NDIM * KDIM / 4;
    const int n4tot = n4x + n4w;
    prep_kernel<<<(n4tot / 2 + 255) / 256, 256>>>(x, w, n4x, n4tot);

    static bool attr_set = false;
    if (!attr_set) {
        cudaFuncSetAttribute(qgemm_fp16, cudaFuncAttributeMaxDynamicSharedMemorySize, SMEM_TOTAL);
        attr_set = true;
    }
    dim3 grid(NDIM / BN, MDIM / BM);   // (32, 32) = 1024 CTAs
    qgemm_fp16<<<grid, 512, SMEM_TOTAL>>>(bias, out);
}

// round 17
// speedup vs baseline: 1.1379x; 1.0071x over previous
#include <cuda_runtime.h>
#include <cuda_fp16.h>
#include <cstdint>

// out[M,N] = x[M,K] @ W[N,K]^T + bias ; M=8192, N=4096, K=1024 (fp32)
// Round 17: GEMM = R11 byte-for-byte (5x measured at 176.4-177.2us = 96% of
// the mma.sync issue floor; every perturbation regressed). Prep: MLP-2
// streaming loads + merged uint4 store (two adjacent float4 -> one 16B store,
// single src/dst select per thread).

#define MDIM 8192
#define NDIM 4096
#define KDIM 1024

#define BM 256
#define BN 128
#define BK 32                 // fp16: 64 B per row per plane
#define STAGES 6
#define NCHUNK (KDIM / BK)    // 32
#define NPAIR (NCHUNK / 2)    // 16

#define APLANEB (BM * 64)     // 16384 B
#define BPLANEB (BN * 64)     // 8192 B
#define OFF_A 0
#define OFF_B (APLANEB)
#define STAGEB (APLANEB + BPLANEB)    // 24576
#define SMEM_TOTAL (STAGES * STAGEB)  // 147456

// XOR swizzle on 16B chunks within 64B rows (conflict-free ldmatrix + cp.async)
#define SWZ(a) ((a) ^ (((a) >> 3) & 0x30))

// ---- static scratch for fp16 operands ----
__device__ __align__(256) __half g_A[MDIM * KDIM];
__device__ __align__(256) __half g_B[NDIM * KDIM];

// ================= PTX helpers (base PTX only) =================
__device__ __forceinline__ uint32_t smem_u32(const void* p) {
    uint32_t a;
    asm("{ .reg .u64 t; cvta.to.shared.u64 t, %1; cvt.u32.u64 %0, t; }" : "=r"(a) : "l"(p));
    return a;
}
__device__ __forceinline__ void cp16(uint32_t dst, const void* src) {
    asm volatile("cp.async.cg.shared.global [%0], [%1], 16;" :: "r"(dst), "l"(src));
}
#define CP_COMMIT() asm volatile("cp.async.commit_group;" ::: "memory")
#define CP_WAIT2()  asm volatile("cp.async.wait_group 2;"  ::: "memory")
#define CP_WAIT0()  asm volatile("cp.async.wait_group 0;"  ::: "memory")

__device__ __forceinline__ void ldm_x4(uint32_t* r, uint32_t addr) {
    asm volatile("ldmatrix.sync.aligned.m8n8.x4.shared.b16 {%0,%1,%2,%3}, [%4];"
        : "=r"(r[0]), "=r"(r[1]), "=r"(r[2]), "=r"(r[3]) : "r"(addr));
}
__device__ __forceinline__ void mma16816(float* d, const uint32_t* a, const uint32_t* b) {
    asm volatile("mma.sync.aligned.m16n8k16.row.col.f32.f16.f16.f32 "
        "{%0,%1,%2,%3}, {%4,%5,%6,%7}, {%8,%9}, {%0,%1,%2,%3};"
        : "+f"(d[0]), "+f"(d[1]), "+f"(d[2]), "+f"(d[3])
        : "r"(a[0]), "r"(a[1]), "r"(a[2]), "r"(a[3]), "r"(b[0]), "r"(b[1]));
}

// ==== prep: fp32 -> fp16, two adjacent float4 loads -> one uint4 store =====
__device__ __forceinline__ uint32_t pack_h2(float lo, float hi) {
    uint32_t r;
    asm("cvt.rn.f16x2.f32 %0, %1, %2;" : "=r"(r) : "f"(hi), "f"(lo));
    return r;
}
__global__ void prep_kernel(const float* __restrict__ x,
                            const float* __restrict__ w,
                            int n4x, int n4tot)
{
    const int i0 = (blockIdx.x * blockDim.x + threadIdx.x) * 2;  // even; pair in same tensor
    if (i0 >= n4tot) return;
    const float* src;
    __half* dst;
    int idx;
    if (i0 < n4x) { src = x; dst = g_A; idx = i0; }              // n4x is even
    else          { src = w; dst = g_B; idx = i0 - n4x; }

    float4 v0 = __ldcs(reinterpret_cast<const float4*>(src) + idx);      // evict-first
    float4 v1 = __ldcs(reinterpret_cast<const float4*>(src) + idx + 1);

    uint4 o;
    o.x = pack_h2(v0.x, v0.y);
    o.y = pack_h2(v0.z, v0.w);
    o.z = pack_h2(v1.x, v1.y);
    o.w = pack_h2(v1.z, v1.w);
    *reinterpret_cast<uint4*>(reinterpret_cast<uint2*>(dst) + idx) = o;  // 16B store
}

// ================= main GEMM kernel (R11, unmodified) =================
__global__ void __launch_bounds__(512, 1)
qgemm_fp16(const float* __restrict__ bias, float* __restrict__ C)
{
    extern __shared__ char smem[];
    const uint32_t sbase = smem_u32(smem);
    const int tid  = threadIdx.x;
    const int wid  = tid >> 5;
    const int lane = tid & 31;
    const int bm = blockIdx.y * BM;
    const int bn = blockIdx.x * BN;
    const int wm = (wid >> 2) * 64;   // warp row offset (0,64,128,192)
    const int wn = (wid & 3) * 32;    // warp col offset (0,32,64,96)

    float acc[4][4][4];
    #pragma unroll
    for (int a = 0; a < 4; a++)
        #pragma unroll
        for (int b = 0; b < 4; b++)
            #pragma unroll
            for (int k = 0; k < 4; k++)
                acc[a][b][k] = 0.0f;

    // loader coords (512 threads: A plane 2 chunks/thread, B plane 1)
    const int a0row = tid >> 2,         a0c = tid & 3;
    const int a1row = (tid + 512) >> 2;
    const uint32_t dswA0 = SWZ((uint32_t)(a0row * 64 + a0c * 16));
    const uint32_t dswA1 = SWZ((uint32_t)(a1row * 64 + a0c * 16));
    const char* pA0 = (const char*)g_A + (size_t)(bm + a0row) * (KDIM * 2) + a0c * 16;
    const char* pA1 = (const char*)g_A + (size_t)(bm + a1row) * (KDIM * 2) + a0c * 16;
    const char* pB  = (const char*)g_B + (size_t)(bn + a0row) * (KDIM * 2) + a0c * 16;

    auto issue = [&](int chunk) {
        const uint32_t sst = sbase + (chunk % STAGES) * STAGEB;
        const size_t ko = (size_t)chunk * (BK * 2);
        cp16(sst + OFF_A + dswA0, pA0 + ko);
        cp16(sst + OFF_A + dswA1, pA1 + ko);
        cp16(sst + OFF_B + dswA0, pB + ko);
        CP_COMMIT();
    };
    issue(0); issue(1); issue(2); issue(3);

    // ldmatrix fragment offsets (plane-relative, swizzled), ks = k16 half
    uint32_t aoff[4][2], boff[2][2];
    #pragma unroll
    for (int mb = 0; mb < 4; mb++)
        #pragma unroll
        for (int ks = 0; ks < 2; ks++)
            aoff[mb][ks] = SWZ((uint32_t)((wm + mb * 16 + (lane & 15)) * 64 +
                                          ks * 32 + (lane >> 4) * 16));
    #pragma unroll
    for (int p = 0; p < 2; p++)
        #pragma unroll
        for (int ks = 0; ks < 2; ks++)
            boff[p][ks] = SWZ((uint32_t)((wn + p * 16 + (lane & 7) + ((lane >> 4) << 3)) * 64 +
                                         ks * 32 + ((lane >> 3) & 1) * 16));

    auto do_ks = [&](int chunk, int ks) {
        const uint32_t sst = sbase + (chunk % STAGES) * STAGEB;
        uint32_t bh[4][2];
        #pragma unroll
        for (int p = 0; p < 2; p++) {
            uint32_t r[4];
            ldm_x4(r, sst + OFF_B + boff[p][ks]);
            bh[p*2][0] = r[0]; bh[p*2][1] = r[1];
            bh[p*2+1][0] = r[2]; bh[p*2+1][1] = r[3];
        }
        #pragma unroll
        for (int mb = 0; mb < 4; mb++) {
            uint32_t ah[4];
            ldm_x4(ah, sst + OFF_A + aoff[mb][ks]);
            #pragma unroll
            for (int nb = 0; nb < 4; nb++)
                mma16816(acc[mb][nb], ah, bh[nb]);
        }
    };

    for (int p = 0; p < NPAIR; p++) {
        const int c = 2 * p;
        if (p == NPAIR - 1) { CP_WAIT0(); } else { CP_WAIT2(); }
        __syncthreads();

        do_ks(c, 0);     do_ks(c, 1);
        do_ks(c + 1, 0); do_ks(c + 1, 1);

        if (c + 4 < NCHUNK) issue(c + 4);
        if (c + 5 < NCHUNK) issue(c + 5);
    }

    // -------- epilogue: + bias, store --------
    const int g  = lane >> 2;
    const int tg = lane & 3;
    #pragma unroll
    for (int mb = 0; mb < 4; mb++) {
        #pragma unroll
        for (int nb = 0; nb < 4; nb++) {
            const int col = bn + wn + nb * 8 + tg * 2;
            const float2 bv = *reinterpret_cast<const float2*>(bias + col);
            const int r0 = bm + wm + mb * 16 + g;
            float2 o0 = {acc[mb][nb][0] + bv.x, acc[mb][nb][1] + bv.y};
            float2 o1 = {acc[mb][nb][2] + bv.x, acc[mb][nb][3] + bv.y};
            *reinterpret_cast<float2*>(C + (size_t)r0 * NDIM + col) = o0;
            *reinterpret_cast<float2*>(C + (size_t)(r0 + 8) * NDIM + col) = o1;
        }
    }
}

// ================= host side =================
extern "C" void kernel_launch(void* const* d_in, const int* in_sizes, int n_in,
                              void* d_out, int out_size)
{
    const float* x    = (const float*)d_in[0];   // [M, K]
    const float* w    = (const float*)d_in[1];   // [N, K]
    const float* bias = (const float*)d_in[2];   // [N]
    float* out        = (float*)d_out;           // [M, N]

    const int n4x = MDIM * KDIM / 4;
    const int n4w = NDIM * KDIM / 4;
    const int n4tot = n4x + n4w;
    prep_kernel<<<(n4tot / 2 + 255) / 256, 256>>>(x, w, n4x, n4tot);

    static bool attr_set = false;
    if (!attr_set) {
        cudaFuncSetAttribute(qgemm_fp16, cudaFuncAttributeMaxDynamicSharedMemorySize, SMEM_TOTAL);
        attr_set = true;
    }
    dim3 grid(NDIM / BN, MDIM / BM);   // (32, 32) = 1024 CTAs
    qgemm_fp16<<<grid, 512, SMEM_TOTAL>>>(bias, out);
}